// round 8
// baseline (speedup 1.0000x reference)
#include <cuda_runtime.h>
#include <cuda_bf16.h>
#include <stdint.h>

#define N_NODES 100000
#define N_EDGES 1200000
#define HID     64
#define TGT     32
#define NLAY    3
#define NGRAPH  500
#define OUTW    (NLAY*TGT)   // 96
#define SCAN_B  1024
#define NBLK    ((N_NODES + SCAN_B - 1)/SCAN_B)   // 98
#define MMAB    ((N_NODES + 127)/128)             // 782

// ---------------------------------------------------------------- scratch
static __device__ float g_feat[N_NODES*HID];
static __device__ float g_A   [N_NODES*HID];
static __device__ float g_h   [N_NODES*HID];
static __device__ float g_y   [N_NODES*HID];
static __device__ float g_gsum [NGRAPH*HID];
static __device__ float g_gvar [NGRAPH*HID];
static __device__ float g_alpha[NGRAPH*HID];
static __device__ float g_beta [NGRAPH*HID];
static __device__ float g_ypool[NGRAPH*HID];
static __device__ float g_cnt  [NGRAPH];
static __device__ int   g_deg  [N_NODES];
static __device__ int   g_off  [N_NODES+1];
static __device__ int   g_cursor[N_NODES];
static __device__ int   g_csr  [N_EDGES];
static __device__ int   g_bsum [NBLK];
// bf16 split weights, transposed [n][k] (k contiguous)
static __device__ __nv_bfloat16 g_cw1h[NLAY*4096], g_cw1l[NLAY*4096];
static __device__ __nv_bfloat16 g_cw2h[NLAY*4096], g_cw2l[NLAY*4096];
static __device__ __nv_bfloat16 g_pw1h[NLAY*4096], g_pw1l[NLAY*4096];

// ---------------------------------------------------------------- helpers
__device__ __forceinline__ void mma16816(float d[4], const uint32_t a[4],
                                         const uint32_t b[2]) {
    asm volatile(
        "mma.sync.aligned.m16n8k16.row.col.f32.bf16.bf16.f32 "
        "{%0,%1,%2,%3}, {%4,%5,%6,%7}, {%8,%9}, {%0,%1,%2,%3};"
        : "+f"(d[0]), "+f"(d[1]), "+f"(d[2]), "+f"(d[3])
        : "r"(a[0]), "r"(a[1]), "r"(a[2]), "r"(a[3]), "r"(b[0]), "r"(b[1]));
}
__device__ __forceinline__ uint32_t packbf2(float x, float y) {
    __nv_bfloat162 t = __halves2bfloat162(__float2bfloat16(x), __float2bfloat16(y));
    return *(uint32_t*)&t;
}
__device__ __forceinline__ void split8(const float v[8], uint4* hi, uint4* lo) {
    uint32_t h[4], l[4];
    #pragma unroll
    for (int q = 0; q < 4; q++) {
        float a = v[2*q], b = v[2*q+1];
        __nv_bfloat16 ha = __float2bfloat16(a), hb = __float2bfloat16(b);
        __nv_bfloat162 hp = __halves2bfloat162(ha, hb);
        h[q] = *(uint32_t*)&hp;
        __nv_bfloat162 lp = __halves2bfloat162(
            __float2bfloat16(a - __bfloat162float(ha)),
            __float2bfloat16(b - __bfloat162float(hb)));
        l[q] = *(uint32_t*)&lp;
    }
    *hi = make_uint4(h[0], h[1], h[2], h[3]);
    *lo = make_uint4(l[0], l[1], l[2], l[3]);
}
__device__ __forceinline__ void redv4(float* p, float4 v) {
    asm volatile("red.global.add.v4.f32 [%0], {%1,%2,%3,%4};"
                 :: "l"(p), "f"(v.x), "f"(v.y), "f"(v.z), "f"(v.w) : "memory");
}

// ---------------------------------------------------------------- setup

__global__ void k_zero_once() {
    int i = blockIdx.x*blockDim.x + threadIdx.x;
    if (i < N_NODES) g_deg[i] = 0;
    if (i < NGRAPH)  g_cnt[i] = 0.f;
    if (i < NGRAPH*HID) { g_gsum[i] = 0.f; g_gvar[i] = 0.f; }
}

__global__ void k_hist(const int* __restrict__ dst) {
    int e = blockIdx.x*blockDim.x + threadIdx.x;
    if (e < N_EDGES) atomicAdd(&g_deg[dst[e]], 1);
}

__global__ void k_count(const int* __restrict__ gid) {
    int i = blockIdx.x*blockDim.x + threadIdx.x;
    if (i < N_NODES) atomicAdd(&g_cnt[gid[i]], 1.0f);
}

__global__ __launch_bounds__(SCAN_B) void k_scan1() {
    __shared__ int wsum[32];
    int i = blockIdx.x*SCAN_B + threadIdx.x;
    int lane = threadIdx.x & 31, wid = threadIdx.x >> 5;
    int v = (i < N_NODES) ? g_deg[i] : 0;
    int s = v;
    #pragma unroll
    for (int o = 1; o < 32; o <<= 1) {
        int t = __shfl_up_sync(~0u, s, o);
        if (lane >= o) s += t;
    }
    if (lane == 31) wsum[wid] = s;
    __syncthreads();
    if (wid == 0) {
        int ws = wsum[lane];
        #pragma unroll
        for (int o = 1; o < 32; o <<= 1) {
            int t = __shfl_up_sync(~0u, ws, o);
            if (lane >= o) ws += t;
        }
        wsum[lane] = ws;
    }
    __syncthreads();
    int excl = s - v + ((wid > 0) ? wsum[wid-1] : 0);
    if (i < N_NODES) g_off[i] = excl;
    if (threadIdx.x == SCAN_B-1) g_bsum[blockIdx.x] = wsum[31];
}

__global__ __launch_bounds__(128) void k_scan2() {
    __shared__ int buf[128];
    int tid = threadIdx.x;
    int v = (tid < NBLK) ? g_bsum[tid] : 0;
    buf[tid] = v;
    __syncthreads();
    #pragma unroll
    for (int o = 1; o < 128; o <<= 1) {
        int t = (tid >= o) ? buf[tid - o] : 0;
        __syncthreads();
        buf[tid] += t;
        __syncthreads();
    }
    if (tid < NBLK) g_bsum[tid] = buf[tid] - v;
    if (tid == 127) g_off[N_NODES] = buf[127];
}

__global__ void k_scan3() {
    int i = blockIdx.x*blockDim.x + threadIdx.x;
    if (i < N_NODES) {
        int o = g_off[i] + g_bsum[i >> 10];
        g_off[i] = o;
        g_cursor[i] = o;
    }
}

__global__ void k_scatter(const int* __restrict__ src, const int* __restrict__ dst) {
    int e = blockIdx.x*blockDim.x + threadIdx.x;
    if (e < N_EDGES) {
        int p = atomicAdd(&g_cursor[dst[e]], 1);
        g_csr[p] = src[e];
    }
}

// transpose + bf16 split of [L][64][64] weights -> dst[l][n*64+k]
__global__ void k_wprep(const float* __restrict__ src,
                        __nv_bfloat16* __restrict__ dh,
                        __nv_bfloat16* __restrict__ dl) {
    int i = blockIdx.x*blockDim.x + threadIdx.x;
    if (i >= NLAY*4096) return;
    int l = i >> 12, r = i & 4095, k = r >> 6, n = r & 63;
    float v = src[i];
    __nv_bfloat16 h = __float2bfloat16(v);
    dh[l*4096 + n*64 + k] = h;
    dl[l*4096 + n*64 + k] = __float2bfloat16(v - __bfloat162float(h));
}

// ------------------------------------------------ aggregation (CSR gather)
__global__ __launch_bounds__(256) void k_agg(const float* __restrict__ x, int use_x,
                                             const float* __restrict__ eps, int l) {
    unsigned t = blockIdx.x*blockDim.x + threadIdx.x;
    unsigned node = t >> 4;
    if (node >= N_NODES) return;
    int j = (int)(t & 15u) << 2;
    const float* __restrict__ f = use_x ? x : g_feat;
    float sc = 1.0f + eps[l];
    float4 acc = *(const float4*)&f[(size_t)node*HID + j];
    acc.x *= sc; acc.y *= sc; acc.z *= sc; acc.w *= sc;
    int b = g_off[node], e = g_off[node+1];
    for (; b + 4 <= e; b += 4) {
        int s0 = g_csr[b], s1 = g_csr[b+1], s2 = g_csr[b+2], s3 = g_csr[b+3];
        float4 v0 = *(const float4*)&f[(size_t)s0*HID + j];
        float4 v1 = *(const float4*)&f[(size_t)s1*HID + j];
        float4 v2 = *(const float4*)&f[(size_t)s2*HID + j];
        float4 v3 = *(const float4*)&f[(size_t)s3*HID + j];
        acc.x += (v0.x + v1.x) + (v2.x + v3.x);
        acc.y += (v0.y + v1.y) + (v2.y + v3.y);
        acc.z += (v0.z + v1.z) + (v2.z + v3.z);
        acc.w += (v0.w + v1.w) + (v2.w + v3.w);
    }
    for (; b < e; b++) {
        int s = g_csr[b];
        float4 v = *(const float4*)&f[(size_t)s*HID + j];
        acc.x += v.x; acc.y += v.y; acc.z += v.z; acc.w += v.w;
    }
    *(float4*)&g_A[(size_t)node*HID + j] = acc;
}

// ============================================================ MMA kernels
// A smem: 128 rows x 72 bf16 stride (144 B). W smem: 64 n-rows x 72 bf16.
#define ARS 144
#define CM_B1  0
#define CM_B2  256
#define CM_AH  512
#define CM_AL  (CM_AH + 128*ARS)            // 18944
#define CM_W1H (CM_AL + 128*ARS)            // 37376
#define CM_W1L (CM_W1H + 64*ARS)            // 46592
#define CM_W2H (CM_W1L + 64*ARS)            // 55808
#define CM_W2L (CM_W2H + 64*ARS)            // 65024
#define CM_TOTAL (CM_W2L + 64*ARS)          // 74240

// warp-level GEMM: 32 rows x 64 cols x 64 K, 3-product bf16 split.
// acc[mt][nt][4]; fragments per mma spec (row.col).
__device__ __forceinline__ void warp_gemm(
    char* smem, int aoffH, int aoffL, int woffH, int woffL,
    int w, int g, int tig, float acc[2][8][4])
{
    #pragma unroll
    for (int kt = 0; kt < 4; kt++) {
        uint32_t ah[2][4], al[2][4];
        const int ka = (kt*16 + tig*2)*2;
        #pragma unroll
        for (int mt = 0; mt < 2; mt++) {
            int rw = w*32 + mt*16 + g;
            ah[mt][0] = *(const uint32_t*)(smem + aoffH + rw*ARS + ka);
            ah[mt][1] = *(const uint32_t*)(smem + aoffH + (rw+8)*ARS + ka);
            ah[mt][2] = *(const uint32_t*)(smem + aoffH + rw*ARS + ka + 16);
            ah[mt][3] = *(const uint32_t*)(smem + aoffH + (rw+8)*ARS + ka + 16);
            al[mt][0] = *(const uint32_t*)(smem + aoffL + rw*ARS + ka);
            al[mt][1] = *(const uint32_t*)(smem + aoffL + (rw+8)*ARS + ka);
            al[mt][2] = *(const uint32_t*)(smem + aoffL + rw*ARS + ka + 16);
            al[mt][3] = *(const uint32_t*)(smem + aoffL + (rw+8)*ARS + ka + 16);
        }
        #pragma unroll
        for (int nt = 0; nt < 8; nt++) {
            uint32_t bh[2], bl[2];
            const char* wb = smem + (nt*8 + g)*ARS + ka;
            bh[0] = *(const uint32_t*)(wb + woffH);
            bh[1] = *(const uint32_t*)(wb + woffH + 16);
            bl[0] = *(const uint32_t*)(wb + woffL);
            bl[1] = *(const uint32_t*)(wb + woffL + 16);
            #pragma unroll
            for (int mt = 0; mt < 2; mt++) {
                mma16816(acc[mt][nt], ah[mt], bh);
                mma16816(acc[mt][nt], ah[mt], bl);
                mma16816(acc[mt][nt], al[mt], bh);
            }
        }
    }
}

__global__ __launch_bounds__(128) void k_conv_mma(
    const float* __restrict__ b1, const float* __restrict__ b2,
    const __nv_bfloat16* __restrict__ w1h, const __nv_bfloat16* __restrict__ w1l,
    const __nv_bfloat16* __restrict__ w2h, const __nv_bfloat16* __restrict__ w2l)
{
    extern __shared__ char smem[];
    const int tid = threadIdx.x;
    const int w = tid >> 5, lane = tid & 31, g = lane >> 2, tig = lane & 3;
    const int row0 = blockIdx.x * 128;

    if (tid < 64) {
        ((float*)(smem + CM_B1))[tid] = b1[tid];
        ((float*)(smem + CM_B2))[tid] = b2[tid];
    }
    // A: load fp32, split, store (row stride 72 bf16)
    #pragma unroll
    for (int it = 0; it < 8; it++) {
        int idx = it*1024 + tid*8;
        int r = idx >> 6, col = idx & 63;
        int row = row0 + r;
        float v[8] = {0,0,0,0,0,0,0,0};
        if (row < N_NODES) {
            const float* p = &g_A[(size_t)row*64 + col];
            float4 a = *(const float4*)p, b = *(const float4*)(p+4);
            v[0]=a.x; v[1]=a.y; v[2]=a.z; v[3]=a.w;
            v[4]=b.x; v[5]=b.y; v[6]=b.z; v[7]=b.w;
        }
        uint4 hi, lo;
        split8(v, &hi, &lo);
        *(uint4*)(smem + CM_AH + r*ARS + col*2) = hi;
        *(uint4*)(smem + CM_AL + r*ARS + col*2) = lo;
    }
    // weights: 4096 bf16 each, 8 per thread per iter
    #pragma unroll
    for (int it = 0; it < 4; it++) {
        int idx = it*1024 + tid*8;
        int n = idx >> 6, k = idx & 63;
        int so = n*ARS + k*2;
        *(uint4*)(smem + CM_W1H + so) = *(const uint4*)&w1h[idx];
        *(uint4*)(smem + CM_W1L + so) = *(const uint4*)&w1l[idx];
        *(uint4*)(smem + CM_W2H + so) = *(const uint4*)&w2h[idx];
        *(uint4*)(smem + CM_W2L + so) = *(const uint4*)&w2l[idx];
    }
    __syncthreads();

    float acc[2][8][4];
    #pragma unroll
    for (int mt = 0; mt < 2; mt++)
        #pragma unroll
        for (int nt = 0; nt < 8; nt++)
            #pragma unroll
            for (int q = 0; q < 4; q++) acc[mt][nt][q] = 0.f;

    warp_gemm(smem, CM_AH, CM_AL, CM_W1H, CM_W1L, w, g, tig, acc);

    // h1 = relu(D + b1) -> split back into AH/AL (warp-private rows)
    const float* b1s = (const float*)(smem + CM_B1);
    #pragma unroll
    for (int mt = 0; mt < 2; mt++) {
        int r0 = w*32 + mt*16 + g;
        #pragma unroll
        for (int nt = 0; nt < 8; nt++) {
            int col = nt*8 + tig*2;
            float vb0 = b1s[col], vb1 = b1s[col+1];
            float v00 = fmaxf(acc[mt][nt][0] + vb0, 0.f);
            float v01 = fmaxf(acc[mt][nt][1] + vb1, 0.f);
            float v10 = fmaxf(acc[mt][nt][2] + vb0, 0.f);
            float v11 = fmaxf(acc[mt][nt][3] + vb1, 0.f);
            uint32_t h0 = packbf2(v00, v01), h1v = packbf2(v10, v11);
            __nv_bfloat162 h0b = *(__nv_bfloat162*)&h0;
            __nv_bfloat162 h1b = *(__nv_bfloat162*)&h1v;
            uint32_t l0 = packbf2(v00 - __bfloat162float(h0b.x),
                                  v01 - __bfloat162float(h0b.y));
            uint32_t l1 = packbf2(v10 - __bfloat162float(h1b.x),
                                  v11 - __bfloat162float(h1b.y));
            *(uint32_t*)(smem + CM_AH + r0*ARS + col*2)     = h0;
            *(uint32_t*)(smem + CM_AH + (r0+8)*ARS + col*2) = h1v;
            *(uint32_t*)(smem + CM_AL + r0*ARS + col*2)     = l0;
            *(uint32_t*)(smem + CM_AL + (r0+8)*ARS + col*2) = l1;
        }
    }
    __syncwarp();

    #pragma unroll
    for (int mt = 0; mt < 2; mt++)
        #pragma unroll
        for (int nt = 0; nt < 8; nt++)
            #pragma unroll
            for (int q = 0; q < 4; q++) acc[mt][nt][q] = 0.f;

    warp_gemm(smem, CM_AH, CM_AL, CM_W2H, CM_W2L, w, g, tig, acc);

    // h = D + b2 -> g_h
    const float* b2s = (const float*)(smem + CM_B2);
    #pragma unroll
    for (int mt = 0; mt < 2; mt++) {
        int r0 = row0 + w*32 + mt*16 + g;
        #pragma unroll
        for (int nt = 0; nt < 8; nt++) {
            int col = nt*8 + tig*2;
            float vb0 = b2s[col], vb1 = b2s[col+1];
            if (r0 < N_NODES)
                *(float2*)&g_h[(size_t)r0*64 + col] =
                    make_float2(acc[mt][nt][0] + vb0, acc[mt][nt][1] + vb1);
            if (r0 + 8 < N_NODES)
                *(float2*)&g_h[(size_t)(r0+8)*64 + col] =
                    make_float2(acc[mt][nt][2] + vb0, acc[mt][nt][3] + vb1);
        }
    }
}

#define PM_B1  0
#define PM_AH  256
#define PM_AL  (PM_AH + 128*ARS)
#define PM_WH  (PM_AL + 128*ARS)
#define PM_WL  (PM_WH + 64*ARS)
#define PM_TOTAL (PM_WL + 64*ARS)

__global__ __launch_bounds__(128) void k_proj_mma(
    const float* __restrict__ pb1,
    const __nv_bfloat16* __restrict__ wh_g, const __nv_bfloat16* __restrict__ wl_g,
    const int* __restrict__ gid)
{
    extern __shared__ char smem[];
    const int tid = threadIdx.x;
    const int w = tid >> 5, lane = tid & 31, g = lane >> 2, tig = lane & 3;
    const int row0 = blockIdx.x * 128;

    if (tid < 64) ((float*)(smem + PM_B1))[tid] = pb1[tid];

    // GraphNorm affine + relu -> g_feat (global) + bf16 split (SMEM)
    #pragma unroll
    for (int it = 0; it < 8; it++) {
        int idx = it*1024 + tid*8;
        int r = idx >> 6, col = idx & 63;
        int row = row0 + r;
        float v[8] = {0,0,0,0,0,0,0,0};
        if (row < N_NODES) {
            int gg = gid[row];
            const float* hp = &g_h[(size_t)row*64 + col];
            const float* ap = &g_alpha[gg*64 + col];
            const float* bp = &g_beta[gg*64 + col];
            float4 h0 = *(const float4*)hp,  h1 = *(const float4*)(hp+4);
            float4 a0 = *(const float4*)ap,  a1 = *(const float4*)(ap+4);
            float4 e0 = *(const float4*)bp,  e1 = *(const float4*)(bp+4);
            v[0] = fmaxf(fmaf(a0.x, h0.x, e0.x), 0.f);
            v[1] = fmaxf(fmaf(a0.y, h0.y, e0.y), 0.f);
            v[2] = fmaxf(fmaf(a0.z, h0.z, e0.z), 0.f);
            v[3] = fmaxf(fmaf(a0.w, h0.w, e0.w), 0.f);
            v[4] = fmaxf(fmaf(a1.x, h1.x, e1.x), 0.f);
            v[5] = fmaxf(fmaf(a1.y, h1.y, e1.y), 0.f);
            v[6] = fmaxf(fmaf(a1.z, h1.z, e1.z), 0.f);
            v[7] = fmaxf(fmaf(a1.w, h1.w, e1.w), 0.f);
            float* fp = &g_feat[(size_t)row*64 + col];
            *(float4*)fp     = make_float4(v[0], v[1], v[2], v[3]);
            *(float4*)(fp+4) = make_float4(v[4], v[5], v[6], v[7]);
        }
        uint4 hi, lo;
        split8(v, &hi, &lo);
        *(uint4*)(smem + PM_AH + r*ARS + col*2) = hi;
        *(uint4*)(smem + PM_AL + r*ARS + col*2) = lo;
    }
    #pragma unroll
    for (int it = 0; it < 4; it++) {
        int idx = it*1024 + tid*8;
        int n = idx >> 6, k = idx & 63;
        int so = n*ARS + k*2;
        *(uint4*)(smem + PM_WH + so) = *(const uint4*)&wh_g[idx];
        *(uint4*)(smem + PM_WL + so) = *(const uint4*)&wl_g[idx];
    }
    __syncthreads();

    float acc[2][8][4];
    #pragma unroll
    for (int mt = 0; mt < 2; mt++)
        #pragma unroll
        for (int nt = 0; nt < 8; nt++)
            #pragma unroll
            for (int q = 0; q < 4; q++) acc[mt][nt][q] = 0.f;

    warp_gemm(smem, PM_AH, PM_AL, PM_WH, PM_WL, w, g, tig, acc);

    // y = relu(D + pb1) -> g_y
    const float* b1s = (const float*)(smem + PM_B1);
    #pragma unroll
    for (int mt = 0; mt < 2; mt++) {
        int r0 = row0 + w*32 + mt*16 + g;
        #pragma unroll
        for (int nt = 0; nt < 8; nt++) {
            int col = nt*8 + tig*2;
            float vb0 = b1s[col], vb1 = b1s[col+1];
            if (r0 < N_NODES)
                *(float2*)&g_y[(size_t)r0*64 + col] =
                    make_float2(fmaxf(acc[mt][nt][0] + vb0, 0.f),
                                fmaxf(acc[mt][nt][1] + vb1, 0.f));
            if (r0 + 8 < N_NODES)
                *(float2*)&g_y[(size_t)(r0+8)*64 + col] =
                    make_float2(fmaxf(acc[mt][nt][2] + vb0, 0.f),
                                fmaxf(acc[mt][nt][3] + vb1, 0.f));
        }
    }
}

// -------------------------------------------- segment sums (sorted gid)
__global__ __launch_bounds__(256) void k_gstat(const int* __restrict__ gid) {
    int tid = threadIdx.x;
    int row0 = blockIdx.x * 64;
    int c0 = (tid & 15) << 2, rg = tid >> 4;
    int base = row0 + rg*4;
    float4 s = make_float4(0,0,0,0), q = s;
    int cb = (base < N_NODES) ? base : (N_NODES - 1);
    int cur = gid[cb];
    #pragma unroll
    for (int r = 0; r < 4; r++) {
        int row = base + r;
        if (row < N_NODES) {
            int g = gid[row];
            float4 h = *(const float4*)&g_h[(size_t)row*64 + c0];
            if (g != cur) {
                redv4(&g_gsum[cur*64 + c0], s);
                redv4(&g_gvar[cur*64 + c0], q);
                s = make_float4(0,0,0,0); q = s; cur = g;
            }
            s.x += h.x; s.y += h.y; s.z += h.z; s.w += h.w;
            q.x += h.x*h.x; q.y += h.y*h.y; q.z += h.z*h.z; q.w += h.w*h.w;
        }
    }
    redv4(&g_gsum[cur*64 + c0], s);
    redv4(&g_gvar[cur*64 + c0], q);
}

__global__ __launch_bounds__(256) void k_pool(const int* __restrict__ gid) {
    int tid = threadIdx.x;
    int row0 = blockIdx.x * 64;
    int c0 = (tid & 15) << 2, rg = tid >> 4;
    int base = row0 + rg*4;
    float4 s = make_float4(0,0,0,0);
    int cb = (base < N_NODES) ? base : (N_NODES - 1);
    int cur = gid[cb];
    #pragma unroll
    for (int r = 0; r < 4; r++) {
        int row = base + r;
        if (row < N_NODES) {
            int g = gid[row];
            float4 y = *(const float4*)&g_y[(size_t)row*64 + c0];
            if (g != cur) {
                redv4(&g_ypool[cur*64 + c0], s);
                s = make_float4(0,0,0,0); cur = g;
            }
            s.x += y.x; s.y += y.y; s.z += y.z; s.w += y.w;
        }
    }
    redv4(&g_ypool[cur*64 + c0], s);
}

// norm coeffs + zero ypool for this layer's pooling
__global__ void k_stats(const float* __restrict__ gns,
                        const float* __restrict__ gnw,
                        const float* __restrict__ gnb) {
    int i = blockIdx.x*blockDim.x + threadIdx.x;
    if (i >= NGRAPH*HID) return;
    int c = i & 63, g = i >> 6;
    float n  = fmaxf(g_cnt[g], 1.f);
    float m  = g_gsum[i] / n;
    float e2 = g_gvar[i] / n;
    float s  = gns[c];
    float var = e2 - m*m*s*(2.f - s);
    float sd  = sqrtf(fmaxf(var, 0.f) + 1e-8f);
    float al  = gnw[c] / sd;
    g_alpha[i] = al;
    g_beta[i]  = gnb[c] - al*m*s;
    g_gsum[i] = 0.f;
    g_gvar[i] = 0.f;
    g_ypool[i] = 0.f;
}

// out[g, l*32+c] = (ypool[g] @ pw2)[c] / max(n,1) + pb2[c]*min(n,1)
__global__ void k_out(const float* __restrict__ pw2, const float* __restrict__ pb2,
                      float* __restrict__ out, int l) {
    int i = blockIdx.x*blockDim.x + threadIdx.x;
    if (i >= NGRAPH*TGT) return;
    int g = i >> 5, c = i & 31;
    float acc = 0.f;
    #pragma unroll 8
    for (int k = 0; k < 64; k++)
        acc = fmaf(g_ypool[g*64 + k], pw2[k*32 + c], acc);
    float n = g_cnt[g];
    out[g*OUTW + l*TGT + c] = acc / fmaxf(n, 1.f) + pb2[c] * fminf(n, 1.f);
}

// ---------------------------------------------------------------- launcher

extern "C" void kernel_launch(void* const* d_in, const int* in_sizes, int n_in,
                              void* d_out, int out_size) {
    const float* x   = (const float*)d_in[0];
    const int*   src = (const int*)  d_in[1];
    const int*   dst = (const int*)  d_in[2];
    const int*   gid = (const int*)  d_in[3];
    const float* eps = (const float*)d_in[4];
    const float* cw1 = (const float*)d_in[5];
    const float* cb1 = (const float*)d_in[6];
    const float* cw2 = (const float*)d_in[7];
    const float* cb2 = (const float*)d_in[8];
    const float* gnw = (const float*)d_in[9];
    const float* gnb = (const float*)d_in[10];
    const float* gns = (const float*)d_in[11];
    const float* pw1 = (const float*)d_in[12];
    const float* pb1 = (const float*)d_in[13];
    const float* pw2 = (const float*)d_in[14];
    const float* pb2 = (const float*)d_in[15];
    float* out = (float*)d_out;

    cudaFuncSetAttribute(k_conv_mma, cudaFuncAttributeMaxDynamicSharedMemorySize, CM_TOTAL);
    cudaFuncSetAttribute(k_proj_mma, cudaFuncAttributeMaxDynamicSharedMemorySize, PM_TOTAL);

    const int EB = (N_EDGES + 255)/256;
    const int NB = (N_NODES + 255)/256;
    const int WB = (NLAY*4096 + 255)/256;
    const int SB = (N_NODES + 63)/64;
    const int AB = (N_NODES*16 + 255)/256;

    k_zero_once<<<NB, 256>>>();
    k_hist<<<EB, 256>>>(dst);
    k_count<<<NB, 256>>>(gid);
    k_scan1<<<NBLK, SCAN_B>>>();
    k_scan2<<<1, 128>>>();
    k_scan3<<<NB, 256>>>();
    k_scatter<<<EB, 256>>>(src, dst);
    k_wprep<<<WB, 256>>>(cw1, g_cw1h, g_cw1l);
    k_wprep<<<WB, 256>>>(cw2, g_cw2h, g_cw2l);
    k_wprep<<<WB, 256>>>(pw1, g_pw1h, g_pw1l);

    for (int l = 0; l < NLAY; l++) {
        int use_x = (l == 0) ? 1 : 0;
        k_agg<<<AB, 256>>>(x, use_x, eps, l);
        k_conv_mma<<<MMAB, 128, CM_TOTAL>>>(cb1 + l*64, cb2 + l*64,
                                            g_cw1h + l*4096, g_cw1l + l*4096,
                                            g_cw2h + l*4096, g_cw2l + l*4096);
        k_gstat<<<SB, 256>>>(gid);
        k_stats<<<(NGRAPH*HID + 255)/256, 256>>>(gns + l*64, gnw + l*64, gnb + l*64);
        k_proj_mma<<<MMAB, 128, PM_TOTAL>>>(pb1 + l*64,
                                            g_pw1h + l*4096, g_pw1l + l*4096, gid);
        k_pool<<<SB, 256>>>(gid);
        k_out<<<(NGRAPH*TGT + 255)/256, 256>>>(pw2 + l*2048, pb2 + l*32, out, l);
    }
}

// round 9
// speedup vs baseline: 1.7782x; 1.7782x over previous
#include <cuda_runtime.h>
#include <stdint.h>

#define N_NODES 100000
#define N_EDGES 1200000
#define HID     64
#define TGT     32
#define NLAY    3
#define NGRAPH  500
#define OUTW    (NLAY*TGT)   // 96
#define SCAN_B  1024
#define NBLK    ((N_NODES + SCAN_B - 1)/SCAN_B)   // 98

typedef unsigned long long ull;

// ---------------------------------------------------------------- scratch
static __device__ float g_feat[N_NODES*HID];
static __device__ float g_A   [N_NODES*HID];
static __device__ float g_h   [N_NODES*HID];
static __device__ float g_gsum [NGRAPH*HID];
static __device__ float g_gvar [NGRAPH*HID];
static __device__ float g_alpha[NGRAPH*HID];
static __device__ float g_beta [NGRAPH*HID];
static __device__ float g_ypool[NGRAPH*HID];
static __device__ float g_cnt  [NGRAPH];
static __device__ int   g_deg  [N_NODES];
static __device__ int   g_off  [N_NODES+1];
static __device__ int   g_cursor[N_NODES];
static __device__ int   g_csr  [N_EDGES];
static __device__ int   g_bsum [NBLK];

// ---------------------------------------------------------------- f32x2
__device__ __forceinline__ ull dup2(float x) {
    ull r; asm("mov.b64 %0, {%1, %1};" : "=l"(r) : "f"(x)); return r;
}
__device__ __forceinline__ ull pk2(float x, float y) {
    ull r; asm("mov.b64 %0, {%1, %2};" : "=l"(r) : "f"(x), "f"(y)); return r;
}
__device__ __forceinline__ float2 up2(ull v) {
    float lo, hi; asm("mov.b64 {%0, %1}, %2;" : "=f"(lo), "=f"(hi) : "l"(v));
    return make_float2(lo, hi);
}
__device__ __forceinline__ ull ffma2(ull a, ull b, ull c) {
    ull d; asm("fma.rn.f32x2 %0, %1, %2, %3;" : "=l"(d) : "l"(a), "l"(b), "l"(c));
    return d;
}

// ---------------------------------------------------------------- setup

__global__ void k_zero_once() {
    int i = blockIdx.x*blockDim.x + threadIdx.x;
    if (i < N_NODES) g_deg[i] = 0;
    if (i < NGRAPH)  g_cnt[i] = 0.f;
    if (i < NGRAPH*HID) { g_gsum[i] = 0.f; g_gvar[i] = 0.f; }
}

__global__ void k_hist(const int* __restrict__ dst) {
    int e = blockIdx.x*blockDim.x + threadIdx.x;
    if (e < N_EDGES) atomicAdd(&g_deg[dst[e]], 1);
}

__global__ void k_count(const int* __restrict__ gid) {
    int i = blockIdx.x*blockDim.x + threadIdx.x;
    if (i < N_NODES) atomicAdd(&g_cnt[gid[i]], 1.0f);
}

// ---------------- two-level exclusive scan of degrees

__global__ __launch_bounds__(SCAN_B) void k_scan1() {
    __shared__ int wsum[32];
    int i = blockIdx.x*SCAN_B + threadIdx.x;
    int lane = threadIdx.x & 31, wid = threadIdx.x >> 5;
    int v = (i < N_NODES) ? g_deg[i] : 0;
    int s = v;
    #pragma unroll
    for (int o = 1; o < 32; o <<= 1) {
        int t = __shfl_up_sync(~0u, s, o);
        if (lane >= o) s += t;
    }
    if (lane == 31) wsum[wid] = s;
    __syncthreads();
    if (wid == 0) {
        int ws = wsum[lane];
        #pragma unroll
        for (int o = 1; o < 32; o <<= 1) {
            int t = __shfl_up_sync(~0u, ws, o);
            if (lane >= o) ws += t;
        }
        wsum[lane] = ws;
    }
    __syncthreads();
    int excl = s - v + ((wid > 0) ? wsum[wid-1] : 0);
    if (i < N_NODES) g_off[i] = excl;
    if (threadIdx.x == SCAN_B-1) g_bsum[blockIdx.x] = wsum[31];
}

__global__ __launch_bounds__(128) void k_scan2() {
    __shared__ int buf[128];
    int tid = threadIdx.x;
    int v = (tid < NBLK) ? g_bsum[tid] : 0;
    buf[tid] = v;
    __syncthreads();
    #pragma unroll
    for (int o = 1; o < 128; o <<= 1) {
        int t = (tid >= o) ? buf[tid - o] : 0;
        __syncthreads();
        buf[tid] += t;
        __syncthreads();
    }
    if (tid < NBLK) g_bsum[tid] = buf[tid] - v;
    if (tid == 127) g_off[N_NODES] = buf[127];
}

__global__ void k_scan3() {
    int i = blockIdx.x*blockDim.x + threadIdx.x;
    if (i < N_NODES) {
        int o = g_off[i] + g_bsum[i >> 10];
        g_off[i] = o;
        g_cursor[i] = o;
    }
}

__global__ void k_scatter(const int* __restrict__ src, const int* __restrict__ dst) {
    int e = blockIdx.x*blockDim.x + threadIdx.x;
    if (e < N_EDGES) {
        int p = atomicAdd(&g_cursor[dst[e]], 1);
        g_csr[p] = src[e];
    }
}

// ------------------------------------------------ aggregation (CSR gather)
// 16 lanes per node, each lane owns 4 columns. A = (1+eps)*feat + sum(neigh)
__global__ __launch_bounds__(256) void k_agg(const float* __restrict__ x, int use_x,
                                             const float* __restrict__ eps, int l) {
    unsigned t = blockIdx.x*blockDim.x + threadIdx.x;
    unsigned node = t >> 4;
    if (node >= N_NODES) return;
    int j = (int)(t & 15u) << 2;
    const float* __restrict__ f = use_x ? x : g_feat;
    float sc = 1.0f + eps[l];
    float4 acc = *(const float4*)&f[(size_t)node*HID + j];
    acc.x *= sc; acc.y *= sc; acc.z *= sc; acc.w *= sc;
    int b = g_off[node], e = g_off[node+1];
    for (; b + 4 <= e; b += 4) {
        int s0 = g_csr[b], s1 = g_csr[b+1], s2 = g_csr[b+2], s3 = g_csr[b+3];
        float4 v0 = *(const float4*)&f[(size_t)s0*HID + j];
        float4 v1 = *(const float4*)&f[(size_t)s1*HID + j];
        float4 v2 = *(const float4*)&f[(size_t)s2*HID + j];
        float4 v3 = *(const float4*)&f[(size_t)s3*HID + j];
        acc.x += (v0.x + v1.x) + (v2.x + v3.x);
        acc.y += (v0.y + v1.y) + (v2.y + v3.y);
        acc.z += (v0.z + v1.z) + (v2.z + v3.z);
        acc.w += (v0.w + v1.w) + (v2.w + v3.w);
    }
    for (; b < e; b++) {
        int s = g_csr[b];
        float4 v = *(const float4*)&f[(size_t)s*HID + j];
        acc.x += v.x; acc.y += v.y; acc.z += v.z; acc.w += v.w;
    }
    *(float4*)&g_A[(size_t)node*HID + j] = acc;
}

// ============================================================ fused kernel 1
// MLP (2 GEMMs, col-pair x 8-row FFMA2 tile) + GraphNorm stats epilogue
__global__ __launch_bounds__(256) void k_conv(
    const float* __restrict__ w1, const float* __restrict__ b1,
    const float* __restrict__ w2, const float* __restrict__ b2,
    const int*   __restrict__ gid)
{
    __shared__ float W1s[4096];
    __shared__ float W2s[4096];
    __shared__ float As[64*68];
    __shared__ float b1s[64], b2s[64];
    __shared__ int   gids[64];

    const int tid  = threadIdx.x;
    const int row0 = blockIdx.x * 64;

    for (int i = tid; i < 4096; i += 256) { W1s[i] = w1[i]; W2s[i] = w2[i]; }
    if (tid < 64) {
        b1s[tid] = b1[tid]; b2s[tid] = b2[tid];
        int r = row0 + tid;
        gids[tid] = (r < N_NODES) ? gid[r] : 0;
    }
    #pragma unroll
    for (int it = 0; it < 4; it++) {
        int i = it*256 + tid;
        int r = i >> 4, kk = (i & 15) << 2;
        int row = row0 + r;
        float4 v = make_float4(0.f,0.f,0.f,0.f);
        if (row < N_NODES) v = *(const float4*)&g_A[(size_t)row*64 + kk];
        *(float4*)&As[r*68 + kk] = v;
    }
    __syncthreads();

    const int cp = tid & 31;   // column pair (2cp, 2cp+1)
    const int wr = tid >> 5;   // rows wr*8 .. wr*8+7
    const float* arow = &As[wr*8*68];

    ull acc[8];
    {
        ull bb = pk2(b1s[2*cp], b1s[2*cp+1]);
        #pragma unroll
        for (int r = 0; r < 8; r++) acc[r] = bb;
    }
    #pragma unroll 4
    for (int k = 0; k < 64; k += 4) {
        ull w0 = *(const ull*)&W1s[(k+0)*64 + 2*cp];
        ull w1v = *(const ull*)&W1s[(k+1)*64 + 2*cp];
        ull w2v = *(const ull*)&W1s[(k+2)*64 + 2*cp];
        ull w3v = *(const ull*)&W1s[(k+3)*64 + 2*cp];
        #pragma unroll
        for (int rr = 0; rr < 8; rr++) {
            float4 a = *(const float4*)&arow[rr*68 + k];
            acc[rr] = ffma2(dup2(a.x), w0,  acc[rr]);
            acc[rr] = ffma2(dup2(a.y), w1v, acc[rr]);
            acc[rr] = ffma2(dup2(a.z), w2v, acc[rr]);
            acc[rr] = ffma2(dup2(a.w), w3v, acc[rr]);
        }
    }
    __syncthreads();
    #pragma unroll
    for (int rr = 0; rr < 8; rr++) {
        float2 h = up2(acc[rr]);
        *(float2*)&As[(wr*8+rr)*68 + 2*cp] =
            make_float2(fmaxf(h.x, 0.f), fmaxf(h.y, 0.f));
    }
    __syncthreads();

    {
        ull bb = pk2(b2s[2*cp], b2s[2*cp+1]);
        #pragma unroll
        for (int r = 0; r < 8; r++) acc[r] = bb;
    }
    #pragma unroll 4
    for (int k = 0; k < 64; k += 4) {
        ull w0 = *(const ull*)&W2s[(k+0)*64 + 2*cp];
        ull w1v = *(const ull*)&W2s[(k+1)*64 + 2*cp];
        ull w2v = *(const ull*)&W2s[(k+2)*64 + 2*cp];
        ull w3v = *(const ull*)&W2s[(k+3)*64 + 2*cp];
        #pragma unroll
        for (int rr = 0; rr < 8; rr++) {
            float4 a = *(const float4*)&arow[rr*68 + k];
            acc[rr] = ffma2(dup2(a.x), w0,  acc[rr]);
            acc[rr] = ffma2(dup2(a.y), w1v, acc[rr]);
            acc[rr] = ffma2(dup2(a.z), w2v, acc[rr]);
            acc[rr] = ffma2(dup2(a.w), w3v, acc[rr]);
        }
    }

    // epilogue: write h, accumulate per-graph sum(h) and sum(h^2)
    float s0=0.f, s1=0.f, q0=0.f, q1=0.f;
    int cur = gids[wr*8];
    #pragma unroll
    for (int rr = 0; rr < 8; rr++) {
        int row = row0 + wr*8 + rr;
        if (row < N_NODES) {
            float2 h = up2(acc[rr]);
            *(float2*)&g_h[(size_t)row*64 + 2*cp] = h;
            int g = gids[wr*8 + rr];
            if (g != cur) {
                atomicAdd(&g_gsum[cur*64 + 2*cp],   s0);
                atomicAdd(&g_gsum[cur*64 + 2*cp+1], s1);
                atomicAdd(&g_gvar[cur*64 + 2*cp],   q0);
                atomicAdd(&g_gvar[cur*64 + 2*cp+1], q1);
                s0=s1=q0=q1=0.f; cur = g;
            }
            s0 += h.x; s1 += h.y; q0 += h.x*h.x; q1 += h.y*h.y;
        }
    }
    atomicAdd(&g_gsum[cur*64 + 2*cp],   s0);
    atomicAdd(&g_gsum[cur*64 + 2*cp+1], s1);
    atomicAdd(&g_gvar[cur*64 + 2*cp],   q0);
    atomicAdd(&g_gvar[cur*64 + 2*cp+1], q1);
}

// ------------------------------------------------ per-(graph,ch) norm coeffs
__global__ void k_stats(const float* __restrict__ gns,
                        const float* __restrict__ gnw,
                        const float* __restrict__ gnb) {
    int i = blockIdx.x*blockDim.x + threadIdx.x;
    if (i >= NGRAPH*HID) return;
    int c = i & 63, g = i >> 6;
    float n  = fmaxf(g_cnt[g], 1.f);
    float m  = g_gsum[i] / n;
    float e2 = g_gvar[i] / n;
    float s  = gns[c];
    float var = e2 - m*m*s*(2.f - s);
    float sd  = sqrtf(fmaxf(var, 0.f) + 1e-8f);
    float al  = gnw[c] / sd;
    g_alpha[i] = al;
    g_beta[i]  = gnb[c] - al*m*s;
    g_gsum[i] = 0.f;
    g_gvar[i] = 0.f;
    g_ypool[i] = 0.f;   // clean for this layer's y-pooling
}

// ============================================================ fused kernel 2
// GraphNorm affine+relu -> proj GEMM1 -> relu -> per-graph y pooling
__global__ __launch_bounds__(256) void k_proj(
    const float* __restrict__ pw1, const float* __restrict__ pb1,
    const int*   __restrict__ gid, int last)
{
    __shared__ float W1s[4096];
    __shared__ float As[64*68];
    __shared__ float b1s[64];
    __shared__ int   gids[64];

    const int tid  = threadIdx.x;
    const int row0 = blockIdx.x * 64;

    for (int i = tid; i < 4096; i += 256) W1s[i] = pw1[i];
    if (tid < 64) {
        b1s[tid] = pb1[tid];
        int r = row0 + tid;
        gids[tid] = (r < N_NODES) ? gid[r] : 0;
    }
    __syncthreads();

    // GraphNorm affine + relu -> As (+ g_feat for next layer unless last)
    #pragma unroll
    for (int it = 0; it < 4; it++) {
        int i = it*256 + tid;
        int r = i >> 4, kk = (i & 15) << 2;
        int row = row0 + r;
        float4 v = make_float4(0.f,0.f,0.f,0.f);
        if (row < N_NODES) {
            int g = gids[r];
            float4 h  = *(const float4*)&g_h[(size_t)row*64 + kk];
            float4 al = *(const float4*)&g_alpha[g*64 + kk];
            float4 be = *(const float4*)&g_beta[g*64 + kk];
            v.x = fmaxf(fmaf(al.x, h.x, be.x), 0.f);
            v.y = fmaxf(fmaf(al.y, h.y, be.y), 0.f);
            v.z = fmaxf(fmaf(al.z, h.z, be.z), 0.f);
            v.w = fmaxf(fmaf(al.w, h.w, be.w), 0.f);
            if (!last) *(float4*)&g_feat[(size_t)row*64 + kk] = v;
        }
        *(float4*)&As[r*68 + kk] = v;
    }
    __syncthreads();

    // GEMM1: 64x64, col-pair (2cp, 2cp+1) x 8 rows per thread
    const int cp = tid & 31;
    const int wr = tid >> 5;
    const float* arow = &As[wr*8*68];
    ull acc[8];
    {
        ull bb = pk2(b1s[2*cp], b1s[2*cp+1]);
        #pragma unroll
        for (int r = 0; r < 8; r++) acc[r] = bb;
    }
    #pragma unroll 4
    for (int k = 0; k < 64; k += 4) {
        ull w0 = *(const ull*)&W1s[(k+0)*64 + 2*cp];
        ull w1v = *(const ull*)&W1s[(k+1)*64 + 2*cp];
        ull w2v = *(const ull*)&W1s[(k+2)*64 + 2*cp];
        ull w3v = *(const ull*)&W1s[(k+3)*64 + 2*cp];
        #pragma unroll
        for (int rr = 0; rr < 8; rr++) {
            float4 a = *(const float4*)&arow[rr*68 + k];
            acc[rr] = ffma2(dup2(a.x), w0,  acc[rr]);
            acc[rr] = ffma2(dup2(a.y), w1v, acc[rr]);
            acc[rr] = ffma2(dup2(a.z), w2v, acc[rr]);
            acc[rr] = ffma2(dup2(a.w), w3v, acc[rr]);
        }
    }

    // pooling epilogue: y = relu(acc) summed per graph -> g_ypool
    float s0 = 0.f, s1 = 0.f;
    int cur = gids[wr*8];
    #pragma unroll
    for (int rr = 0; rr < 8; rr++) {
        int row = row0 + wr*8 + rr;
        if (row < N_NODES) {
            float2 p = up2(acc[rr]);
            float y0 = fmaxf(p.x, 0.f), y1 = fmaxf(p.y, 0.f);
            int g = gids[wr*8 + rr];
            if (g != cur) {
                atomicAdd(&g_ypool[cur*64 + 2*cp],   s0);
                atomicAdd(&g_ypool[cur*64 + 2*cp+1], s1);
                s0 = 0.f; s1 = 0.f; cur = g;
            }
            s0 += y0; s1 += y1;
        }
    }
    atomicAdd(&g_ypool[cur*64 + 2*cp],   s0);
    atomicAdd(&g_ypool[cur*64 + 2*cp+1], s1);
}

// out[g, l*32+c] = (ypool[g] @ pw2)[c] / max(n,1) + pb2[c] * min(n,1)
__global__ void k_out(const float* __restrict__ pw2, const float* __restrict__ pb2,
                      float* __restrict__ out, int l) {
    int i = blockIdx.x*blockDim.x + threadIdx.x;
    if (i >= NGRAPH*TGT) return;
    int g = i >> 5, c = i & 31;
    float acc = 0.f;
    #pragma unroll 8
    for (int k = 0; k < 64; k++)
        acc = fmaf(g_ypool[g*64 + k], pw2[k*32 + c], acc);
    float n = g_cnt[g];
    out[g*OUTW + l*TGT + c] = acc / fmaxf(n, 1.f) + pb2[c] * fminf(n, 1.f);
}

// ---------------------------------------------------------------- launcher

extern "C" void kernel_launch(void* const* d_in, const int* in_sizes, int n_in,
                              void* d_out, int out_size) {
    const float* x   = (const float*)d_in[0];
    const int*   src = (const int*)  d_in[1];
    const int*   dst = (const int*)  d_in[2];
    const int*   gid = (const int*)  d_in[3];
    const float* eps = (const float*)d_in[4];
    const float* cw1 = (const float*)d_in[5];
    const float* cb1 = (const float*)d_in[6];
    const float* cw2 = (const float*)d_in[7];
    const float* cb2 = (const float*)d_in[8];
    const float* gnw = (const float*)d_in[9];
    const float* gnb = (const float*)d_in[10];
    const float* gns = (const float*)d_in[11];
    const float* pw1 = (const float*)d_in[12];
    const float* pb1 = (const float*)d_in[13];
    const float* pw2 = (const float*)d_in[14];
    const float* pb2 = (const float*)d_in[15];
    float* out = (float*)d_out;

    const int EB = (N_EDGES + 255)/256;
    const int NB = (N_NODES + 255)/256;

    k_zero_once<<<NB, 256>>>();
    k_hist<<<EB, 256>>>(dst);
    k_count<<<NB, 256>>>(gid);
    k_scan1<<<NBLK, SCAN_B>>>();
    k_scan2<<<1, 128>>>();
    k_scan3<<<NB, 256>>>();
    k_scatter<<<EB, 256>>>(src, dst);

    const int GB = (N_NODES + 63)/64;
    const int AB = (N_NODES*16 + 255)/256;

    for (int l = 0; l < NLAY; l++) {
        int use_x = (l == 0) ? 1 : 0;
        int last  = (l == NLAY-1) ? 1 : 0;
        k_agg<<<AB, 256>>>(x, use_x, eps, l);
        k_conv<<<GB, 256>>>(cw1 + l*4096, cb1 + l*64,
                            cw2 + l*4096, cb2 + l*64, gid);
        k_stats<<<(NGRAPH*HID + 255)/256, 256>>>(gns + l*64, gnw + l*64, gnb + l*64);
        k_proj<<<GB, 256>>>(pw1 + l*4096, pb1 + l*64, gid, last);
        k_out<<<(NGRAPH*TGT + 255)/256, 256>>>(pw2 + l*2048, pb2 + l*32, out, l);
    }
}